// round 4
// baseline (speedup 1.0000x reference)
#include <cuda_runtime.h>
#include <math.h>

#define VOCAB 32000
#define EMB   256
#define UNITS 1024
#define NB    64     // batch
#define NT    256    // time steps
#define G3    3072   // 3*UNITS
#define REC_BLOCKS 128
#define KC    32     // k-chunk for h staging

typedef unsigned long long ull;

// ---------------- scratch ---------------------------------------------------------
__device__ float g_gx[(size_t)2 * NT * NB * G3];   // packed gate-major inputs
__device__ float g_W [(size_t)2 * EMB * G3];       // packed input weights
__device__ float g_U [(size_t)2 * UNITS * G3];     // packed recurrent weights
__device__ float g_h [2][2][UNITS][NB];            // TRANSPOSED: [dir][pingpong][u][b]
__device__ unsigned char g_mask[2][NT][NB];
__device__ unsigned g_bar_count;                   // monotonic arrivals
__device__ unsigned g_bar_gen;                     // released generation

// ---------------- packed f32x2 helpers --------------------------------------------
__device__ __forceinline__ void ffma2(ull& d, ull a, ull b) {
    asm("fma.rn.f32x2 %0, %1, %2, %0;" : "+l"(d) : "l"(a), "l"(b));
}
__device__ __forceinline__ float2 unpack2(ull v) {
    float2 f;
    asm("mov.b64 {%0, %1}, %2;" : "=f"(f.x), "=f"(f.y) : "l"(v));
    return f;
}

// ---------------- fence-light grid barrier ----------------------------------------
__device__ __forceinline__ void grid_barrier(unsigned target) {
    __syncthreads();
    if (threadIdx.x == 0) {
        unsigned prev;
        asm volatile("atom.acq_rel.gpu.add.u32 %0, [%1], 1;"
                     : "=r"(prev) : "l"(&g_bar_count) : "memory");
        if (prev == target * REC_BLOCKS - 1u) {
            asm volatile("st.release.gpu.u32 [%0], %1;"
                         :: "l"(&g_bar_gen), "r"(target) : "memory");
        } else {
            unsigned g;
            do {
                asm volatile("ld.acquire.gpu.u32 %0, [%1];"
                             : "=r"(g) : "l"(&g_bar_gen) : "memory");
            } while (g < target);
        }
    }
    __syncthreads();
}

// ---------------- prep: pack U/W unit-major, masks, h init (transposed) -----------
__global__ void prep_kernel(const int* __restrict__ x, const float* __restrict__ hidden,
                            const float* __restrict__ Wf, const float* __restrict__ Uf,
                            const float* __restrict__ Wb, const float* __restrict__ Ub) {
    const long long NU = 2LL * UNITS * G3;
    const long long NW = 2LL * EMB * G3;
    const long long NM = 2LL * NT * NB;
    const long long NH = 2LL * NB * UNITS;
    const long long total = NU + NW + NM + NH;
    const long long stride = (long long)gridDim.x * blockDim.x;
    for (long long i = (long long)blockIdx.x * blockDim.x + threadIdx.x; i < total; i += stride) {
        if (i < NU) {
            long long dir = i / ((long long)UNITS * G3);
            long long rem = i - dir * (long long)UNITS * G3;
            int k = (int)(rem / G3);
            int p = (int)(rem % G3);
            const float* U = dir ? Ub : Uf;
            g_U[i] = U[(long long)k * G3 + (p % 3) * UNITS + p / 3];
        } else if (i < NU + NW) {
            long long j = i - NU;
            long long dir = j / ((long long)EMB * G3);
            long long rem = j - dir * (long long)EMB * G3;
            int k = (int)(rem / G3);
            int p = (int)(rem % G3);
            const float* W = dir ? Wb : Wf;
            g_W[j] = W[(long long)k * G3 + (p % 3) * UNITS + p / 3];
        } else if (i < NU + NW + NM) {
            long long j = i - NU - NW;
            int dir = (int)(j / (NT * NB));
            int rem = (int)(j % (NT * NB));
            int s = rem / NB, b = rem % NB;
            int t = dir ? (NT - 1 - s) : s;
            g_mask[dir][s][b] = (x[b * NT + t] != 0) ? 1 : 0;
        } else {
            long long j = i - NU - NW - NM;
            int dir = (int)(j / (NB * UNITS));
            int rem = (int)(j % (NB * UNITS));
            int u = rem / NB, b = rem % NB;
            g_h[dir][0][u][b] = hidden[b * UNITS + u];
        }
    }
    if (blockIdx.x == 0 && threadIdx.x == 0) { g_bar_count = 0u; g_bar_gen = 0u; }
}

// ---------------- gx = gather(emb, x) @ W_packed + b_in (col-packed f32x2) --------
__global__ __launch_bounds__(256) void gx_kernel(const int* __restrict__ x,
                                                 const float* __restrict__ emb,
                                                 const float* __restrict__ bf_in,
                                                 const float* __restrict__ bb_in) {
    const int ct  = blockIdx.x;
    const int t   = blockIdx.y;
    const int dir = blockIdx.z;
    const int tid = threadIdx.x;
    const int pbase = ct * 64;
    const int tx = tid & 15, ty = tid >> 4;
    const int tx4 = tx << 2, ty4 = ty << 2;

    __shared__ float2 As2[16][66];   // dup-staged A (batch values duplicated)
    __shared__ float  Ws[16][68];
    __shared__ int    toks[64];

    if (tid < 64) {
        int tt = dir ? (NT - 1 - t) : t;
        toks[tid] = x[tid * NT + tt];
    }
    __syncthreads();

    const float* Wsrc = g_W + (size_t)dir * EMB * G3;
    ull cc[2][4];
#pragma unroll
    for (int p = 0; p < 2; p++)
#pragma unroll
        for (int i = 0; i < 4; i++) cc[p][i] = 0ull;

    for (int k0 = 0; k0 < EMB; k0 += 16) {
        {   // A tile: 64 rows (batch) x 16 k, gathered from emb, DUPLICATED
            int r   = tid >> 2;
            int kk4 = (tid & 3) << 2;
            const float4 v = *(const float4*)(emb + (size_t)toks[r] * EMB + k0 + kk4);
            As2[kk4 + 0][r] = make_float2(v.x, v.x);
            As2[kk4 + 1][r] = make_float2(v.y, v.y);
            As2[kk4 + 2][r] = make_float2(v.z, v.z);
            As2[kk4 + 3][r] = make_float2(v.w, v.w);
        }
        {   // W tile: 16 k x 64 packed cols
            int kk = tid >> 4;
            int p4 = (tid & 15) << 2;
            *(float4*)&Ws[kk][p4] = *(const float4*)(Wsrc + (size_t)(k0 + kk) * G3 + pbase + p4);
        }
        __syncthreads();
#pragma unroll
        for (int kk = 0; kk < 16; kk++) {
            ull w0 = *(const ull*)&Ws[kk][tx4];
            ull w1 = *(const ull*)&Ws[kk][tx4 + 2];
            ull a0 = *(const ull*)&As2[kk][ty4 + 0];
            ull a1 = *(const ull*)&As2[kk][ty4 + 1];
            ull a2 = *(const ull*)&As2[kk][ty4 + 2];
            ull a3 = *(const ull*)&As2[kk][ty4 + 3];
            ffma2(cc[0][0], a0, w0); ffma2(cc[1][0], a0, w1);
            ffma2(cc[0][1], a1, w0); ffma2(cc[1][1], a1, w1);
            ffma2(cc[0][2], a2, w0); ffma2(cc[1][2], a2, w1);
            ffma2(cc[0][3], a3, w0); ffma2(cc[1][3], a3, w1);
        }
        __syncthreads();
    }

    const float* bsrc = dir ? bb_in : bf_in;
    float bin[4];
#pragma unroll
    for (int j = 0; j < 4; j++) {
        int p = pbase + tx4 + j;
        bin[j] = bsrc[(p % 3) * UNITS + p / 3];
    }
    float* gxbase = g_gx + ((size_t)(dir * NT + t) * NB) * G3;
#pragma unroll
    for (int i = 0; i < 4; i++) {
        float2 p0 = unpack2(cc[0][i]);
        float2 p1 = unpack2(cc[1][i]);
        int b = ty4 + i;
        float4 o = make_float4(p0.x + bin[0], p0.y + bin[1],
                               p1.x + bin[2], p1.y + bin[3]);
        *(float4*)(gxbase + (size_t)b * G3 + pbase + tx4) = o;
    }
}

// ---------------- persistent recurrent kernel + fused final-state GEMM ------------
// 128 blocks = 2 dirs x 64 unit-tiles (16 units = 48 packed cols). U (192KB) in smem.
// h staged DUPLICATED (f32x2 pairs) in KC=32 chunks, double buffered.
// Accumulators packed over COLUMNS: thread = 2 units x 2 batch rows.
#define REC_US (48 * UNITS)                              // 49152 floats
#define REC_HB (KC * NB * 2)                             // 4096 floats per dup buffer
#define REC_SMEM_BYTES ((REC_US + 2 * REC_HB) * 4)       // 229376 B

__global__ __launch_bounds__(256) void recurrent_kernel(const float* __restrict__ bf_rec,
                                                        const float* __restrict__ bb_rec,
                                                        const float* __restrict__ Wp,
                                                        const float* __restrict__ bp,
                                                        float* __restrict__ out) {
    extern __shared__ float sm[];
    float* us  = sm;                  // [1024][48] U tile
    float* hsA = sm + REC_US;         // [KC][NB] duplicated pairs
    float* hsB = hsA + REC_HB;

    const int blk   = blockIdx.x;
    const int dir   = blk >> 6;
    const int utile = blk & 63;
    const int pbase = utile * 48;
    const int ubase = utile * 16;
    const int tid = threadIdx.x;
    const int tx = tid & 7;           // unit-pair index (2 units each)
    const int ty = tid >> 3;          // 0..31, 2 batch rows each
    const int b0 = ty << 1;
    const int u0 = ubase + (tx << 1);
    const int u1 = u0 + 1;

    const float* brec = dir ? bb_rec : bf_rec;
    const float bz0 = brec[u0],             bz1 = brec[u1];
    const float br0 = brec[UNITS + u0],     br1 = brec[UNITS + u1];
    const float bh0 = brec[2 * UNITS + u0], bh1 = brec[2 * UNITS + u1];

    // staging indices: thread loads 8 consecutive batch values at one k row
    const int kst = tid >> 3;          // 0..31 local k
    const int bst = (tid & 7) << 3;    // batch offset 0..56

    // ---- load U tile to smem once ----
    {
        const float* Up = g_U + (size_t)dir * UNITS * G3 + pbase;
        for (int i = tid; i < REC_US / 4; i += 256) {
            int k = i / 12, c4 = (i - k * 12) << 2;
            *(float4*)&us[k * 48 + c4] = *(const float4*)(Up + (size_t)k * G3 + c4);
        }
    }
    __syncthreads();

    const float* hbase = &g_h[dir][0][0][0];
    const size_t ppsz  = (size_t)UNITS * NB;

    for (int s = 0; s < NT; s++) {
        const float* hcur = hbase + (size_t)(s & 1) * ppsz;
        float*       hnxt = (float*)hbase + (size_t)((s + 1) & 1) * ppsz;

        // ---- prefetch epilogue operands (consumed ~20K cycles later) ----
        const float* gxb = g_gx + ((size_t)(dir * NT + s) * NB) * G3 + pbase + tx * 6;
        float2 g0[2], g1[2], g2[2];
#pragma unroll
        for (int i = 0; i < 2; i++) {
            const float2* gp = (const float2*)(gxb + (size_t)(b0 + i) * G3);
            g0[i] = __ldcs(gp); g1[i] = __ldcs(gp + 1); g2[i] = __ldcs(gp + 2);
        }
        float2 hp0 = __ldcg((const float2*)(hcur + (size_t)u0 * NB + b0));
        float2 hp1 = __ldcg((const float2*)(hcur + (size_t)u1 * NB + b0));
        uchar2 m2  = *(const uchar2*)&g_mask[dir][s][b0];

        ull acc[3][2];
#pragma unroll
        for (int p = 0; p < 3; p++) { acc[p][0] = 0ull; acc[p][1] = 0ull; }

        // ---- stage chunk 0 (duplicated pairs) ----
        float4 v0 = __ldcg((const float4*)(hcur + (size_t)kst * NB + bst));
        float4 v1 = __ldcg((const float4*)(hcur + (size_t)kst * NB + bst + 4));
        {
            float* dst = hsA + (kst * NB + bst) * 2;
            *(float4*)(dst + 0)  = make_float4(v0.x, v0.x, v0.y, v0.y);
            *(float4*)(dst + 4)  = make_float4(v0.z, v0.z, v0.w, v0.w);
            *(float4*)(dst + 8)  = make_float4(v1.x, v1.x, v1.y, v1.y);
            *(float4*)(dst + 12) = make_float4(v1.z, v1.z, v1.w, v1.w);
        }
        __syncthreads();

        for (int c = 0; c < UNITS / KC; c++) {
            if (c + 1 < UNITS / KC) {
                v0 = __ldcg((const float4*)(hcur + (size_t)((c + 1) * KC + kst) * NB + bst));
                v1 = __ldcg((const float4*)(hcur + (size_t)((c + 1) * KC + kst) * NB + bst + 4));
            }
            const float* hb = (c & 1) ? hsB : hsA;
            const float* ur = us + c * KC * 48 + tx * 6;
#pragma unroll 16
            for (int kk = 0; kk < KC; kk++) {
                ull hd0 = *(const ull*)(hb + kk * (NB * 2) + b0 * 2);
                ull hd1 = *(const ull*)(hb + kk * (NB * 2) + b0 * 2 + 2);
                ull U0 = *(const ull*)(ur + 0);
                ull U1 = *(const ull*)(ur + 2);
                ull U2 = *(const ull*)(ur + 4);
                ffma2(acc[0][0], hd0, U0); ffma2(acc[1][0], hd0, U1); ffma2(acc[2][0], hd0, U2);
                ffma2(acc[0][1], hd1, U0); ffma2(acc[1][1], hd1, U1); ffma2(acc[2][1], hd1, U2);
                ur += 48;
            }
            if (c + 1 < UNITS / KC) {
                float* hw = ((c + 1) & 1) ? hsB : hsA;
                float* dst = hw + (kst * NB + bst) * 2;
                *(float4*)(dst + 0)  = make_float4(v0.x, v0.x, v0.y, v0.y);
                *(float4*)(dst + 4)  = make_float4(v0.z, v0.z, v0.w, v0.w);
                *(float4*)(dst + 8)  = make_float4(v1.x, v1.x, v1.y, v1.y);
                *(float4*)(dst + 12) = make_float4(v1.z, v1.z, v1.w, v1.w);
            }
            __syncthreads();
        }

        // ---- GRU update: 2 units x 2 batch rows ----
        const int tt = dir ? (NT - 1 - s) : s;
        const float hp0v[2] = {hp0.x, hp0.y};
        const float hp1v[2] = {hp1.x, hp1.y};
        const unsigned char mv[2] = {m2.x, m2.y};
        float n0[2], n1[2];
#pragma unroll
        for (int i = 0; i < 2; i++) {
            float2 aP0 = unpack2(acc[0][i]);   // (z_u0, r_u0)
            float2 aP1 = unpack2(acc[1][i]);   // (h_u0, z_u1)
            float2 aP2 = unpack2(acc[2][i]);   // (r_u1, h_u1)
            float z0 = 1.f / (1.f + expf(-(g0[i].x + aP0.x + bz0)));
            float r0 = 1.f / (1.f + expf(-(g0[i].y + aP0.y + br0)));
            float h0 = tanhf(g1[i].x + r0 * (aP1.x + bh0));
            float z1 = 1.f / (1.f + expf(-(g1[i].y + aP1.y + bz1)));
            float r1 = 1.f / (1.f + expf(-(g2[i].x + aP2.x + br1)));
            float h1 = tanhf(g2[i].y + r1 * (aP2.y + bh1));
            float hn0 = z0 * hp0v[i] + (1.f - z0) * h0;
            float hn1 = z1 * hp1v[i] + (1.f - z1) * h1;
            if (!mv[i]) { hn0 = hp0v[i]; hn1 = hp1v[i]; }
            n0[i] = hn0; n1[i] = hn1;
            out[((size_t)(b0 + i) * NT + tt) * (2 * UNITS) + dir * UNITS + u0] = hn0;
            out[((size_t)(b0 + i) * NT + tt) * (2 * UNITS) + dir * UNITS + u1] = hn1;
        }
        *(float2*)(hnxt + (size_t)u0 * NB + b0) = make_float2(n0[0], n0[1]);
        *(float2*)(hnxt + (size_t)u1 * NB + b0) = make_float2(n1[0], n1[1]);

        grid_barrier((unsigned)(s + 1));
    }

    // ---- fused final state: tanh(concat(hf,hb) @ Wp + bp) ----
    {
        float* sst = sm;                  // reuse U region: [128][NB] staging
        const int tx8 = tid & 7;
        const int tyS = tid >> 3;         // 0..31, 2 batch rows each
        const int ocol = blk * 8 + tx8;   // 128 blocks x 8 = 1024 output cols
        const float* wp = Wp + ocol;
        ull acc = 0;
        for (int k0 = 0; k0 < 2 * UNITS; k0 += 128) {
            __syncthreads();
#pragma unroll
            for (int j = 0; j < 8; j++) {
                int f = tid + j * 256;
                int kk = f >> 4, b4 = (f & 15) << 2;
                int k = k0 + kk;
                float4 v = __ldcg((const float4*)(&g_h[k >> 10][0][k & 1023][b4]));
                *(float4*)&sst[kk * NB + b4] = v;
            }
            __syncthreads();
#pragma unroll 8
            for (int kk = 0; kk < 128; kk++) {
                float w = __ldg(wp + (size_t)(k0 + kk) * UNITS);
                ull wv;
                asm("mov.b64 %0, {%1, %1};" : "=l"(wv) : "f"(w));
                ull hh = *(const ull*)(sst + kk * NB + tyS * 2);
                ffma2(acc, hh, wv);
            }
        }
        float2 aa = unpack2(acc);
        float bpv = bp[ocol];
        const size_t so = (size_t)NB * NT * (2 * UNITS);
        out[so + (size_t)(tyS * 2 + 0) * UNITS + ocol] = tanhf(aa.x + bpv);
        out[so + (size_t)(tyS * 2 + 1) * UNITS + ocol] = tanhf(aa.y + bpv);
    }
}

// ---------------- launch ----------------------------------------------------------
extern "C" void kernel_launch(void* const* d_in, const int* in_sizes, int n_in,
                              void* d_out, int out_size) {
    (void)in_sizes; (void)n_in; (void)out_size;
    const int*   x      = (const int*)  d_in[0];
    const float* hidden = (const float*)d_in[1];
    const float* emb    = (const float*)d_in[2];
    const float* Wf     = (const float*)d_in[3];
    const float* Uf     = (const float*)d_in[4];
    const float* bf_in  = (const float*)d_in[5];
    const float* bf_rec = (const float*)d_in[6];
    const float* Wb     = (const float*)d_in[7];
    const float* Ub     = (const float*)d_in[8];
    const float* bb_in  = (const float*)d_in[9];
    const float* bb_rec = (const float*)d_in[10];
    const float* Wp     = (const float*)d_in[11];
    const float* bp     = (const float*)d_in[12];
    float* out = (float*)d_out;

    cudaFuncSetAttribute(recurrent_kernel,
                         cudaFuncAttributeMaxDynamicSharedMemorySize, REC_SMEM_BYTES);

    prep_kernel<<<4096, 256>>>(x, hidden, Wf, Uf, Wb, Ub);
    dim3 ggx(G3 / 64, NT, 2);
    gx_kernel<<<ggx, 256>>>(x, emb, bf_in, bb_in);
    recurrent_kernel<<<REC_BLOCKS, 256, REC_SMEM_BYTES>>>(bf_rec, bb_rec, Wp, bp, out);
}

// round 5
// speedup vs baseline: 1.0004x; 1.0004x over previous
#include <cuda_runtime.h>
#include <math.h>

#define VOCAB 32000
#define EMB   256
#define UNITS 1024
#define NB    64     // batch
#define NT    256    // time steps
#define G3    3072   // 3*UNITS
#define REC_BLOCKS 128
#define KC    32     // k-chunk for h staging

typedef unsigned long long ull;

// ---------------- scratch ---------------------------------------------------------
__device__ float g_gx[(size_t)2 * NT * NB * G3];   // packed gate-major inputs
__device__ float g_W [(size_t)2 * EMB * G3];       // packed input weights
__device__ float g_U [(size_t)2 * UNITS * G3];     // packed recurrent weights
__device__ float g_h [2][2][UNITS][NB];            // TRANSPOSED: [dir][pingpong][u][b]
__device__ unsigned char g_mask[2][NT][NB];
__device__ unsigned g_bar_count;                   // monotonic arrivals
__device__ unsigned g_bar_gen;                     // released generation

// ---------------- packed f32x2 helpers --------------------------------------------
__device__ __forceinline__ void ffma2(ull& d, ull a, ull b) {
    asm("fma.rn.f32x2 %0, %1, %2, %0;" : "+l"(d) : "l"(a), "l"(b));
}
__device__ __forceinline__ float2 unpack2(ull v) {
    float2 f;
    asm("mov.b64 {%0, %1}, %2;" : "=f"(f.x), "=f"(f.y) : "l"(v));
    return f;
}

// ---------------- fence-light grid barrier ----------------------------------------
__device__ __forceinline__ void grid_barrier(unsigned target) {
    __syncthreads();
    if (threadIdx.x == 0) {
        unsigned prev;
        asm volatile("atom.acq_rel.gpu.add.u32 %0, [%1], 1;"
                     : "=r"(prev) : "l"(&g_bar_count) : "memory");
        if (prev == target * REC_BLOCKS - 1u) {
            asm volatile("st.release.gpu.u32 [%0], %1;"
                         :: "l"(&g_bar_gen), "r"(target) : "memory");
        } else {
            unsigned g;
            do {
                asm volatile("ld.acquire.gpu.u32 %0, [%1];"
                             : "=r"(g) : "l"(&g_bar_gen) : "memory");
            } while (g < target);
        }
    }
    __syncthreads();
}

// ---------------- prep: pack U/W unit-major, masks, h init (transposed) -----------
__global__ void prep_kernel(const int* __restrict__ x, const float* __restrict__ hidden,
                            const float* __restrict__ Wf, const float* __restrict__ Uf,
                            const float* __restrict__ Wb, const float* __restrict__ Ub) {
    const long long NU = 2LL * UNITS * G3;
    const long long NW = 2LL * EMB * G3;
    const long long NM = 2LL * NT * NB;
    const long long NH = 2LL * NB * UNITS;
    const long long total = NU + NW + NM + NH;
    const long long stride = (long long)gridDim.x * blockDim.x;
    for (long long i = (long long)blockIdx.x * blockDim.x + threadIdx.x; i < total; i += stride) {
        if (i < NU) {
            long long dir = i / ((long long)UNITS * G3);
            long long rem = i - dir * (long long)UNITS * G3;
            int k = (int)(rem / G3);
            int p = (int)(rem % G3);
            const float* U = dir ? Ub : Uf;
            g_U[i] = U[(long long)k * G3 + (p % 3) * UNITS + p / 3];
        } else if (i < NU + NW) {
            long long j = i - NU;
            long long dir = j / ((long long)EMB * G3);
            long long rem = j - dir * (long long)EMB * G3;
            int k = (int)(rem / G3);
            int p = (int)(rem % G3);
            const float* W = dir ? Wb : Wf;
            g_W[j] = W[(long long)k * G3 + (p % 3) * UNITS + p / 3];
        } else if (i < NU + NW + NM) {
            long long j = i - NU - NW;
            int dir = (int)(j / (NT * NB));
            int rem = (int)(j % (NT * NB));
            int s = rem / NB, b = rem % NB;
            int t = dir ? (NT - 1 - s) : s;
            g_mask[dir][s][b] = (x[b * NT + t] != 0) ? 1 : 0;
        } else {
            long long j = i - NU - NW - NM;
            int dir = (int)(j / (NB * UNITS));
            int rem = (int)(j % (NB * UNITS));
            int u = rem / NB, b = rem % NB;
            g_h[dir][0][u][b] = hidden[b * UNITS + u];
        }
    }
    if (blockIdx.x == 0 && threadIdx.x == 0) { g_bar_count = 0u; g_bar_gen = 0u; }
}

// ---------------- gx = gather(emb, x) @ W_packed + b_in (col-packed f32x2) --------
__global__ __launch_bounds__(256) void gx_kernel(const int* __restrict__ x,
                                                 const float* __restrict__ emb,
                                                 const float* __restrict__ bf_in,
                                                 const float* __restrict__ bb_in) {
    const int ct  = blockIdx.x;
    const int t   = blockIdx.y;
    const int dir = blockIdx.z;
    const int tid = threadIdx.x;
    const int pbase = ct * 64;
    const int tx = tid & 15, ty = tid >> 4;
    const int tx4 = tx << 2, ty4 = ty << 2;

    __shared__ float2 As2[16][66];   // dup-staged A (batch values duplicated)
    __shared__ float  Ws[16][68];
    __shared__ int    toks[64];

    if (tid < 64) {
        int tt = dir ? (NT - 1 - t) : t;
        toks[tid] = x[tid * NT + tt];
    }
    __syncthreads();

    const float* Wsrc = g_W + (size_t)dir * EMB * G3;
    ull cc[2][4];
#pragma unroll
    for (int p = 0; p < 2; p++)
#pragma unroll
        for (int i = 0; i < 4; i++) cc[p][i] = 0ull;

    for (int k0 = 0; k0 < EMB; k0 += 16) {
        {   // A tile: 64 rows (batch) x 16 k, gathered from emb, DUPLICATED
            int r   = tid >> 2;
            int kk4 = (tid & 3) << 2;
            const float4 v = *(const float4*)(emb + (size_t)toks[r] * EMB + k0 + kk4);
            As2[kk4 + 0][r] = make_float2(v.x, v.x);
            As2[kk4 + 1][r] = make_float2(v.y, v.y);
            As2[kk4 + 2][r] = make_float2(v.z, v.z);
            As2[kk4 + 3][r] = make_float2(v.w, v.w);
        }
        {   // W tile: 16 k x 64 packed cols
            int kk = tid >> 4;
            int p4 = (tid & 15) << 2;
            *(float4*)&Ws[kk][p4] = *(const float4*)(Wsrc + (size_t)(k0 + kk) * G3 + pbase + p4);
        }
        __syncthreads();
#pragma unroll
        for (int kk = 0; kk < 16; kk++) {
            ull w0 = *(const ull*)&Ws[kk][tx4];
            ull w1 = *(const ull*)&Ws[kk][tx4 + 2];
            ull a0 = *(const ull*)&As2[kk][ty4 + 0];
            ull a1 = *(const ull*)&As2[kk][ty4 + 1];
            ull a2 = *(const ull*)&As2[kk][ty4 + 2];
            ull a3 = *(const ull*)&As2[kk][ty4 + 3];
            ffma2(cc[0][0], a0, w0); ffma2(cc[1][0], a0, w1);
            ffma2(cc[0][1], a1, w0); ffma2(cc[1][1], a1, w1);
            ffma2(cc[0][2], a2, w0); ffma2(cc[1][2], a2, w1);
            ffma2(cc[0][3], a3, w0); ffma2(cc[1][3], a3, w1);
        }
        __syncthreads();
    }

    const float* bsrc = dir ? bb_in : bf_in;
    float bin[4];
#pragma unroll
    for (int j = 0; j < 4; j++) {
        int p = pbase + tx4 + j;
        bin[j] = bsrc[(p % 3) * UNITS + p / 3];
    }
    float* gxbase = g_gx + ((size_t)(dir * NT + t) * NB) * G3;
#pragma unroll
    for (int i = 0; i < 4; i++) {
        float2 p0 = unpack2(cc[0][i]);
        float2 p1 = unpack2(cc[1][i]);
        int b = ty4 + i;
        float4 o = make_float4(p0.x + bin[0], p0.y + bin[1],
                               p1.x + bin[2], p1.y + bin[3]);
        *(float4*)(gxbase + (size_t)b * G3 + pbase + tx4) = o;
    }
}

// ---------------- persistent recurrent kernel + fused final-state GEMM ------------
// 128 blocks = 2 dirs x 64 unit-tiles (16 units = 48 packed cols). U (192KB) in smem.
// h staged DUPLICATED (f32x2 pairs) in KC=32 chunks, double buffered.
// Accumulators packed over COLUMNS: thread = 2 units x 2 batch rows.
#define REC_US (48 * UNITS)                              // 49152 floats
#define REC_HB (KC * NB * 2)                             // 4096 floats per dup buffer
#define REC_SMEM_BYTES ((REC_US + 2 * REC_HB) * 4)       // 229376 B

__global__ __launch_bounds__(256) void recurrent_kernel(const float* __restrict__ bf_rec,
                                                        const float* __restrict__ bb_rec,
                                                        const float* __restrict__ Wp,
                                                        const float* __restrict__ bp,
                                                        float* __restrict__ out) {
    extern __shared__ float sm[];
    float* us  = sm;                  // [1024][48] U tile
    float* hsA = sm + REC_US;         // [KC][NB] duplicated pairs
    float* hsB = hsA + REC_HB;

    const int blk   = blockIdx.x;
    const int dir   = blk >> 6;
    const int utile = blk & 63;
    const int pbase = utile * 48;
    const int ubase = utile * 16;
    const int tid = threadIdx.x;
    const int tx = tid & 7;           // unit-pair index (2 units each)
    const int ty = tid >> 3;          // 0..31, 2 batch rows each
    const int b0 = ty << 1;
    const int u0 = ubase + (tx << 1);
    const int u1 = u0 + 1;

    const float* brec = dir ? bb_rec : bf_rec;
    const float bz0 = brec[u0],             bz1 = brec[u1];
    const float br0 = brec[UNITS + u0],     br1 = brec[UNITS + u1];
    const float bh0 = brec[2 * UNITS + u0], bh1 = brec[2 * UNITS + u1];

    // staging indices: thread loads 8 consecutive batch values at one k row
    const int kst = tid >> 3;          // 0..31 local k
    const int bst = (tid & 7) << 3;    // batch offset 0..56

    // ---- load U tile to smem once ----
    {
        const float* Up = g_U + (size_t)dir * UNITS * G3 + pbase;
        for (int i = tid; i < REC_US / 4; i += 256) {
            int k = i / 12, c4 = (i - k * 12) << 2;
            *(float4*)&us[k * 48 + c4] = *(const float4*)(Up + (size_t)k * G3 + c4);
        }
    }
    __syncthreads();

    const float* hbase = &g_h[dir][0][0][0];
    const size_t ppsz  = (size_t)UNITS * NB;

    for (int s = 0; s < NT; s++) {
        const float* hcur = hbase + (size_t)(s & 1) * ppsz;
        float*       hnxt = (float*)hbase + (size_t)((s + 1) & 1) * ppsz;

        // ---- prefetch epilogue operands (consumed ~20K cycles later) ----
        const float* gxb = g_gx + ((size_t)(dir * NT + s) * NB) * G3 + pbase + tx * 6;
        float2 g0[2], g1[2], g2[2];
#pragma unroll
        for (int i = 0; i < 2; i++) {
            const float2* gp = (const float2*)(gxb + (size_t)(b0 + i) * G3);
            g0[i] = __ldcs(gp); g1[i] = __ldcs(gp + 1); g2[i] = __ldcs(gp + 2);
        }
        float2 hp0 = __ldcg((const float2*)(hcur + (size_t)u0 * NB + b0));
        float2 hp1 = __ldcg((const float2*)(hcur + (size_t)u1 * NB + b0));
        uchar2 m2  = *(const uchar2*)&g_mask[dir][s][b0];

        ull acc[3][2];
#pragma unroll
        for (int p = 0; p < 3; p++) { acc[p][0] = 0ull; acc[p][1] = 0ull; }

        // ---- stage chunk 0 (duplicated pairs) ----
        float4 v0 = __ldcg((const float4*)(hcur + (size_t)kst * NB + bst));
        float4 v1 = __ldcg((const float4*)(hcur + (size_t)kst * NB + bst + 4));
        {
            float* dst = hsA + (kst * NB + bst) * 2;
            *(float4*)(dst + 0)  = make_float4(v0.x, v0.x, v0.y, v0.y);
            *(float4*)(dst + 4)  = make_float4(v0.z, v0.z, v0.w, v0.w);
            *(float4*)(dst + 8)  = make_float4(v1.x, v1.x, v1.y, v1.y);
            *(float4*)(dst + 12) = make_float4(v1.z, v1.z, v1.w, v1.w);
        }
        __syncthreads();

        for (int c = 0; c < UNITS / KC; c++) {
            if (c + 1 < UNITS / KC) {
                v0 = __ldcg((const float4*)(hcur + (size_t)((c + 1) * KC + kst) * NB + bst));
                v1 = __ldcg((const float4*)(hcur + (size_t)((c + 1) * KC + kst) * NB + bst + 4));
            }
            const float* hb = (c & 1) ? hsB : hsA;
            const float* ur = us + c * KC * 48 + tx * 6;
#pragma unroll 16
            for (int kk = 0; kk < KC; kk++) {
                ull hd0 = *(const ull*)(hb + kk * (NB * 2) + b0 * 2);
                ull hd1 = *(const ull*)(hb + kk * (NB * 2) + b0 * 2 + 2);
                ull U0 = *(const ull*)(ur + 0);
                ull U1 = *(const ull*)(ur + 2);
                ull U2 = *(const ull*)(ur + 4);
                ffma2(acc[0][0], hd0, U0); ffma2(acc[1][0], hd0, U1); ffma2(acc[2][0], hd0, U2);
                ffma2(acc[0][1], hd1, U0); ffma2(acc[1][1], hd1, U1); ffma2(acc[2][1], hd1, U2);
                ur += 48;
            }
            if (c + 1 < UNITS / KC) {
                float* hw = ((c + 1) & 1) ? hsB : hsA;
                float* dst = hw + (kst * NB + bst) * 2;
                *(float4*)(dst + 0)  = make_float4(v0.x, v0.x, v0.y, v0.y);
                *(float4*)(dst + 4)  = make_float4(v0.z, v0.z, v0.w, v0.w);
                *(float4*)(dst + 8)  = make_float4(v1.x, v1.x, v1.y, v1.y);
                *(float4*)(dst + 12) = make_float4(v1.z, v1.z, v1.w, v1.w);
            }
            __syncthreads();
        }

        // ---- GRU update: 2 units x 2 batch rows ----
        const int tt = dir ? (NT - 1 - s) : s;
        const float hp0v[2] = {hp0.x, hp0.y};
        const float hp1v[2] = {hp1.x, hp1.y};
        const unsigned char mv[2] = {m2.x, m2.y};
        float n0[2], n1[2];
#pragma unroll
        for (int i = 0; i < 2; i++) {
            float2 aP0 = unpack2(acc[0][i]);   // (z_u0, r_u0)
            float2 aP1 = unpack2(acc[1][i]);   // (h_u0, z_u1)
            float2 aP2 = unpack2(acc[2][i]);   // (r_u1, h_u1)
            float z0 = 1.f / (1.f + expf(-(g0[i].x + aP0.x + bz0)));
            float r0 = 1.f / (1.f + expf(-(g0[i].y + aP0.y + br0)));
            float h0 = tanhf(g1[i].x + r0 * (aP1.x + bh0));
            float z1 = 1.f / (1.f + expf(-(g1[i].y + aP1.y + bz1)));
            float r1 = 1.f / (1.f + expf(-(g2[i].x + aP2.x + br1)));
            float h1 = tanhf(g2[i].y + r1 * (aP2.y + bh1));
            float hn0 = z0 * hp0v[i] + (1.f - z0) * h0;
            float hn1 = z1 * hp1v[i] + (1.f - z1) * h1;
            if (!mv[i]) { hn0 = hp0v[i]; hn1 = hp1v[i]; }
            n0[i] = hn0; n1[i] = hn1;
            out[((size_t)(b0 + i) * NT + tt) * (2 * UNITS) + dir * UNITS + u0] = hn0;
            out[((size_t)(b0 + i) * NT + tt) * (2 * UNITS) + dir * UNITS + u1] = hn1;
        }
        *(float2*)(hnxt + (size_t)u0 * NB + b0) = make_float2(n0[0], n0[1]);
        *(float2*)(hnxt + (size_t)u1 * NB + b0) = make_float2(n1[0], n1[1]);

        grid_barrier((unsigned)(s + 1));
    }

    // ---- fused final state: tanh(concat(hf,hb) @ Wp + bp) ----
    {
        float* sst = sm;                  // reuse U region: [128][NB] staging
        const int tx8 = tid & 7;
        const int tyS = tid >> 3;         // 0..31, 2 batch rows each
        const int ocol = blk * 8 + tx8;   // 128 blocks x 8 = 1024 output cols
        const float* wp = Wp + ocol;
        ull acc = 0;
        for (int k0 = 0; k0 < 2 * UNITS; k0 += 128) {
            __syncthreads();
#pragma unroll
            for (int j = 0; j < 8; j++) {
                int f = tid + j * 256;
                int kk = f >> 4, b4 = (f & 15) << 2;
                int k = k0 + kk;
                float4 v = __ldcg((const float4*)(&g_h[k >> 10][0][k & 1023][b4]));
                *(float4*)&sst[kk * NB + b4] = v;
            }
            __syncthreads();
#pragma unroll 8
            for (int kk = 0; kk < 128; kk++) {
                float w = __ldg(wp + (size_t)(k0 + kk) * UNITS);
                ull wv;
                asm("mov.b64 %0, {%1, %1};" : "=l"(wv) : "f"(w));
                ull hh = *(const ull*)(sst + kk * NB + tyS * 2);
                ffma2(acc, hh, wv);
            }
        }
        float2 aa = unpack2(acc);
        float bpv = bp[ocol];
        const size_t so = (size_t)NB * NT * (2 * UNITS);
        out[so + (size_t)(tyS * 2 + 0) * UNITS + ocol] = tanhf(aa.x + bpv);
        out[so + (size_t)(tyS * 2 + 1) * UNITS + ocol] = tanhf(aa.y + bpv);
    }
}

// ---------------- launch ----------------------------------------------------------
extern "C" void kernel_launch(void* const* d_in, const int* in_sizes, int n_in,
                              void* d_out, int out_size) {
    (void)in_sizes; (void)n_in; (void)out_size;
    const int*   x      = (const int*)  d_in[0];
    const float* hidden = (const float*)d_in[1];
    const float* emb    = (const float*)d_in[2];
    const float* Wf     = (const float*)d_in[3];
    const float* Uf     = (const float*)d_in[4];
    const float* bf_in  = (const float*)d_in[5];
    const float* bf_rec = (const float*)d_in[6];
    const float* Wb     = (const float*)d_in[7];
    const float* Ub     = (const float*)d_in[8];
    const float* bb_in  = (const float*)d_in[9];
    const float* bb_rec = (const float*)d_in[10];
    const float* Wp     = (const float*)d_in[11];
    const float* bp     = (const float*)d_in[12];
    float* out = (float*)d_out;

    cudaFuncSetAttribute(recurrent_kernel,
                         cudaFuncAttributeMaxDynamicSharedMemorySize, REC_SMEM_BYTES);

    prep_kernel<<<4096, 256>>>(x, hidden, Wf, Uf, Wb, Ub);
    dim3 ggx(G3 / 64, NT, 2);
    gx_kernel<<<ggx, 256>>>(x, emb, bf_in, bb_in);
    recurrent_kernel<<<REC_BLOCKS, 256, REC_SMEM_BYTES>>>(bf_rec, bb_rec, Wp, bp, out);
}

// round 8
// speedup vs baseline: 3.1772x; 3.1759x over previous
#include <cuda_runtime.h>
#include <cuda_bf16.h>
#include <cstdint>
#include <math.h>

#define VOCAB 32000
#define EMB   256
#define UNITS 1024
#define NB    64
#define NT    256
#define G3    3072
#define REC_BLOCKS 128

typedef unsigned long long ull;

// ---------------- device scratch ---------------------------------------------------
__device__ float g_gx[(size_t)2 * NT * NB * G3];         // packed gate-major inputs
__device__ float g_W [(size_t)2 * EMB * G3];             // packed input weights (fp32)
__device__ __nv_bfloat16 g_ubfT[2][2][G3][UNITS];        // [split][dir][p][k] U^T hi/lo
__device__ float g_h [2][2][NB][UNITS];                  // fp32 h, [dir][pp][b][u]
__device__ __nv_bfloat16 g_hbf[2][2][2][NB][UNITS];      // [split][dir][pp][b][u]
__device__ unsigned char g_mask[2][NT][NB];
__device__ unsigned g_bar_count;
__device__ unsigned g_bar_gen;

// ---------------- helpers -----------------------------------------------------------
__device__ __forceinline__ void ffma2(ull& d, ull a, ull b) {
    asm("fma.rn.f32x2 %0, %1, %2, %0;" : "+l"(d) : "l"(a), "l"(b));
}
__device__ __forceinline__ float2 unpack2(ull v) {
    float2 f;
    asm("mov.b64 {%0, %1}, %2;" : "=f"(f.x), "=f"(f.y) : "l"(v));
    return f;
}
__device__ __forceinline__ uint32_t smem_u32(const void* p) {
    uint32_t a;
    asm("{ .reg .u64 t; cvta.to.shared.u64 t, %1; cvt.u32.u64 %0, t; }" : "=r"(a) : "l"(p));
    return a;
}

#define CP_ASYNC16(dst, src) \
    asm volatile("cp.async.cg.shared.global [%0], [%1], 16;" :: "r"(dst), "l"(src) : "memory")
#define CP_COMMIT() asm volatile("cp.async.commit_group;" ::: "memory")
#define CP_WAIT0()  asm volatile("cp.async.wait_group 0;" ::: "memory")

#define LDMATRIX_X4(r0, r1, r2, r3, addr) \
    asm volatile("ldmatrix.sync.aligned.m8n8.x4.shared.b16 {%0,%1,%2,%3}, [%4];" \
                 : "=r"(r0), "=r"(r1), "=r"(r2), "=r"(r3) : "r"(addr))

#define MMA_BF16(c, a0, a1, a2, a3, b0, b1) \
    asm volatile("mma.sync.aligned.m16n8k16.row.col.f32.bf16.bf16.f32 " \
                 "{%0,%1,%2,%3}, {%4,%5,%6,%7}, {%8,%9}, {%0,%1,%2,%3};" \
                 : "+f"((c)[0]), "+f"((c)[1]), "+f"((c)[2]), "+f"((c)[3]) \
                 : "r"(a0), "r"(a1), "r"(a2), "r"(a3), "r"(b0), "r"(b1))

// ---------------- grid barrier ------------------------------------------------------
__device__ __forceinline__ void grid_barrier(unsigned target) {
    __syncthreads();
    if (threadIdx.x == 0) {
        unsigned prev;
        asm volatile("atom.acq_rel.gpu.add.u32 %0, [%1], 1;"
                     : "=r"(prev) : "l"(&g_bar_count) : "memory");
        if (prev == target * REC_BLOCKS - 1u) {
            asm volatile("st.release.gpu.u32 [%0], %1;"
                         :: "l"(&g_bar_gen), "r"(target) : "memory");
        } else {
            unsigned g;
            do {
                asm volatile("ld.acquire.gpu.u32 %0, [%1];"
                             : "=r"(g) : "l"(&g_bar_gen) : "memory");
            } while (g < target);
        }
    }
    __syncthreads();
}

// ---------------- prep ---------------------------------------------------------------
__global__ void prep_kernel(const int* __restrict__ x, const float* __restrict__ hidden,
                            const float* __restrict__ Wf, const float* __restrict__ Uf,
                            const float* __restrict__ Wb, const float* __restrict__ Ub) {
    const long long NUBF = 2LL * 2 * G3 * UNITS;
    const long long NW   = 2LL * EMB * G3;
    const long long NM   = 2LL * NT * NB;
    const long long NH   = 2LL * NB * UNITS;
    const long long NHBF = 2LL * 2 * NB * UNITS;
    const long long total = NUBF + NW + NM + NH + NHBF;
    const long long stride = (long long)gridDim.x * blockDim.x;
    for (long long i = (long long)blockIdx.x * blockDim.x + threadIdx.x; i < total; i += stride) {
        if (i < NUBF) {
            int split = (int)(i / (2LL * G3 * UNITS));
            long long r1 = i - (long long)split * 2 * G3 * UNITS;
            int dir = (int)(r1 / ((long long)G3 * UNITS));
            long long r2 = r1 - (long long)dir * G3 * UNITS;
            int p = (int)(r2 / UNITS);
            int k = (int)(r2 % UNITS);
            const float* U = dir ? Ub : Uf;
            float val = U[(long long)k * G3 + (p % 3) * UNITS + p / 3];
            __nv_bfloat16 hi = __float2bfloat16(val);
            if (split == 0) g_ubfT[0][dir][p][k] = hi;
            else            g_ubfT[1][dir][p][k] = __float2bfloat16(val - __bfloat162float(hi));
        } else if (i < NUBF + NW) {
            long long j = i - NUBF;
            int dir = (int)(j / ((long long)EMB * G3));
            long long rem = j - (long long)dir * EMB * G3;
            int k = (int)(rem / G3);
            int p = (int)(rem % G3);
            const float* W = dir ? Wb : Wf;
            g_W[j] = W[(long long)k * G3 + (p % 3) * UNITS + p / 3];
        } else if (i < NUBF + NW + NM) {
            long long j = i - NUBF - NW;
            int dir = (int)(j / (NT * NB));
            int rem = (int)(j % (NT * NB));
            int s = rem / NB, b = rem % NB;
            int t = dir ? (NT - 1 - s) : s;
            g_mask[dir][s][b] = (x[b * NT + t] != 0) ? 1 : 0;
        } else if (i < NUBF + NW + NM + NH) {
            long long j = i - NUBF - NW - NM;
            int dir = (int)(j / (NB * UNITS));
            int rem = (int)(j % (NB * UNITS));
            int b = rem / UNITS, u = rem % UNITS;
            g_h[dir][0][b][u] = hidden[b * UNITS + u];
        } else {
            long long j = i - NUBF - NW - NM - NH;
            int split = (int)(j / (2LL * NB * UNITS));
            long long r1 = j - (long long)split * 2 * NB * UNITS;
            int dir = (int)(r1 / (NB * UNITS));
            int rem = (int)(r1 % (NB * UNITS));
            int b = rem / UNITS, u = rem % UNITS;
            float val = hidden[b * UNITS + u];
            __nv_bfloat16 hi = __float2bfloat16(val);
            if (split == 0) g_hbf[0][dir][0][b][u] = hi;
            else            g_hbf[1][dir][0][b][u] = __float2bfloat16(val - __bfloat162float(hi));
        }
    }
    if (blockIdx.x == 0 && threadIdx.x == 0) { g_bar_count = 0u; g_bar_gen = 0u; }
}

// ---------------- gx kernel (round-2 proven version) --------------------------------
__global__ __launch_bounds__(256) void gx_kernel(const int* __restrict__ x,
                                                 const float* __restrict__ emb,
                                                 const float* __restrict__ bf_in,
                                                 const float* __restrict__ bb_in) {
    const int ct  = blockIdx.x;
    const int t   = blockIdx.y;
    const int dir = blockIdx.z;
    const int tid = threadIdx.x;
    const int pbase = ct * 64;
    const int tx = tid & 15, ty = tid >> 4;
    const int tx4 = tx << 2, ty4 = ty << 2;

    __shared__ float As[16][68];
    __shared__ float Ws[16][68];
    __shared__ int   toks[64];

    if (tid < 64) {
        int tt = dir ? (NT - 1 - t) : t;
        toks[tid] = x[tid * NT + tt];
    }
    __syncthreads();

    const float* Wsrc = g_W + (size_t)dir * EMB * G3;
    ull c00 = 0, c01 = 0, c02 = 0, c03 = 0;
    ull c10 = 0, c11 = 0, c12 = 0, c13 = 0;

    for (int k0 = 0; k0 < EMB; k0 += 16) {
        {
            int r   = tid >> 2;
            int kk4 = (tid & 3) << 2;
            const float4 v = *(const float4*)(emb + (size_t)toks[r] * EMB + k0 + kk4);
            As[kk4 + 0][r] = v.x; As[kk4 + 1][r] = v.y;
            As[kk4 + 2][r] = v.z; As[kk4 + 3][r] = v.w;
        }
        {
            int kk = tid >> 4;
            int p4 = (tid & 15) << 2;
            *(float4*)&Ws[kk][p4] = *(const float4*)(Wsrc + (size_t)(k0 + kk) * G3 + pbase + p4);
        }
        __syncthreads();
#pragma unroll
        for (int kk = 0; kk < 16; kk++) {
            ull a01 = *(const ull*)&As[kk][ty4];
            ull a23 = *(const ull*)&As[kk][ty4 + 2];
            float4 w = *(const float4*)&Ws[kk][tx4];
            ull W0, W1, W2, W3;
            asm("mov.b64 %0, {%1, %1};" : "=l"(W0) : "f"(w.x));
            asm("mov.b64 %0, {%1, %1};" : "=l"(W1) : "f"(w.y));
            asm("mov.b64 %0, {%1, %1};" : "=l"(W2) : "f"(w.z));
            asm("mov.b64 %0, {%1, %1};" : "=l"(W3) : "f"(w.w));
            ffma2(c00, a01, W0); ffma2(c01, a01, W1); ffma2(c02, a01, W2); ffma2(c03, a01, W3);
            ffma2(c10, a23, W0); ffma2(c11, a23, W1); ffma2(c12, a23, W2); ffma2(c13, a23, W3);
        }
        __syncthreads();
    }

    const float* bsrc = dir ? bb_in : bf_in;
    float bin[4];
#pragma unroll
    for (int j = 0; j < 4; j++) {
        int p = pbase + tx4 + j;
        bin[j] = bsrc[(p % 3) * UNITS + p / 3];
    }
    float2 u00 = unpack2(c00), u01 = unpack2(c01), u02 = unpack2(c02), u03 = unpack2(c03);
    float2 u10 = unpack2(c10), u11 = unpack2(c11), u12 = unpack2(c12), u13 = unpack2(c13);
    float rows[4][4] = {
        {u00.x, u01.x, u02.x, u03.x},
        {u00.y, u01.y, u02.y, u03.y},
        {u10.x, u11.x, u12.x, u13.x},
        {u10.y, u11.y, u12.y, u13.y},
    };
    float* gxbase = g_gx + ((size_t)(dir * NT + t) * NB) * G3;
#pragma unroll
    for (int i = 0; i < 4; i++) {
        int b = ty4 + i;
        float4 o = make_float4(rows[i][0] + bin[0], rows[i][1] + bin[1],
                               rows[i][2] + bin[2], rows[i][3] + bin[3]);
        *(float4*)(gxbase + (size_t)b * G3 + pbase + tx4) = o;
    }
}

// ---------------- persistent HMMA recurrent kernel -----------------------------------
// 128 blocks = 2 dirs x 64 unit-tiles (16 units = 48 packed cols).
// Per step: C[64x48] = h[64x1024] @ Ut[48x1024]^T via m16n8k16 bf16 mma, 3-term split.
// smem: U frags 196608 | A h-chunks 2 slots x 16384 | bias 192
#define UFRAG_BYTES 196608
#define ABUF_OFF    196608u
#define BIAS_OFF    229376u
#define REC_SMEM_BYTES 229568

__global__ __launch_bounds__(256, 1) void recurrent_kernel(const float* __restrict__ bf_rec,
                                                           const float* __restrict__ bb_rec,
                                                           const float* __restrict__ Wp,
                                                           const float* __restrict__ bp,
                                                           float* __restrict__ out) {
    extern __shared__ char smx[];
    const uint32_t smb = smem_u32(smx);

    const int blk   = blockIdx.x;
    const int dir   = blk >> 6;
    const int utile = blk & 63;
    const int pbase = utile * 48;
    const int ubase = utile * 16;
    const int tid  = threadIdx.x;
    const int wid  = tid >> 5;
    const int lane = tid & 31;
    const int mi = wid & 3;          // warp M-tile (16 rows of batch)
    const int nj = wid >> 2;         // warp N-half (3 n8-tiles of 24 cols)
    const int gid = lane >> 2;
    const int tig = lane & 3;

    // ---- bias into smem (packed-col order) ----
    if (tid < 48) {
        const float* brec = dir ? bb_rec : bf_rec;
        ((float*)(smx + BIAS_OFF))[tid] = brec[(tid % 3) * UNITS + ubase + tid / 3];
    }

    // ---- build fragment-ordered U in smem: [ks 0..63][ntile 0..5][split][lane] x 8B ----
    for (int e = wid; e < 768; e += 8) {
        int ks = e / 12;
        int r  = e % 12;
        int nt = r >> 1;
        int sp = r & 1;
        int p  = pbase + nt * 8 + gid;
        const __nv_bfloat16* up = &g_ubfT[sp][dir][p][ks * 16 + 2 * tig];
        uint32_t b0 = *(const uint32_t*)up;          // k = 2tig, 2tig+1
        uint32_t b1 = *(const uint32_t*)(up + 8);    // k = 2tig+8, +9
        ull v = (ull)b0 | ((ull)b1 << 32);
        *(ull*)(smx + ((size_t)e * 32 + lane) * 8) = v;
    }
    __syncthreads();

    const int b_ep = tid & 63;       // epilogue batch row
    const int usub = tid >> 6;       // epilogue unit group (4 units)

    for (int s = 0; s < NT; s++) {
        const int pp  = s & 1;
        const int ppn = pp ^ 1;

        // ---- prefetch epilogue operands ----
        float gxv[12];
        {
            const float* gxr = g_gx + ((size_t)(dir * NT + s) * NB + b_ep) * G3 + pbase + usub * 12;
#pragma unroll
            for (int q = 0; q < 3; q++)
                *(float4*)&gxv[q * 4] = __ldcs((const float4*)(gxr + q * 4));
        }
        float hp[4];
        *(float4*)hp = __ldcg((const float4*)(&g_h[dir][pp][b_ep][ubase + usub * 4]));
        const int m = g_mask[dir][s][b_ep];

        // ---- stage chunk 0 ----
        {
#pragma unroll
            for (int j = 0; j < 4; j++) {
                int f = tid + j * 256;
                int sp = f >> 9, row = (f >> 3) & 63, seg = f & 7;
                const void* src = &g_hbf[sp][dir][pp][row][seg * 8];
                uint32_t dst = smb + ABUF_OFF + (uint32_t)sp * 8192u
                             + (uint32_t)(row * 128) + (uint32_t)((seg ^ (row & 7)) * 16);
                CP_ASYNC16(dst, src);
            }
            CP_COMMIT();
        }

        float c[3][4];
#pragma unroll
        for (int i = 0; i < 3; i++) { c[i][0] = 0.f; c[i][1] = 0.f; c[i][2] = 0.f; c[i][3] = 0.f; }

        const int arow = mi * 16 + (lane & 15);
        const int acb  = lane >> 4;

        for (int ci = 0; ci < 16; ci++) {
            CP_WAIT0();
            __syncthreads();
            if (ci < 15) {
                const int slot = (ci + 1) & 1;
#pragma unroll
                for (int j = 0; j < 4; j++) {
                    int f = tid + j * 256;
                    int sp = f >> 9, row = (f >> 3) & 63, seg = f & 7;
                    const void* src = &g_hbf[sp][dir][pp][row][(ci + 1) * 64 + seg * 8];
                    uint32_t dst = smb + ABUF_OFF + (uint32_t)slot * 16384u + (uint32_t)sp * 8192u
                                 + (uint32_t)(row * 128) + (uint32_t)((seg ^ (row & 7)) * 16);
                    CP_ASYNC16(dst, src);
                }
                CP_COMMIT();
            }
            const uint32_t abase = smb + ABUF_OFF + (uint32_t)(ci & 1) * 16384u
                                 + (uint32_t)(arow * 128);
#pragma unroll
            for (int ks = 0; ks < 4; ks++) {
                const int seg = ks * 2 + acb;
                const uint32_t sw = (uint32_t)((seg ^ (arow & 7)) * 16);
                uint32_t ah0, ah1, ah2, ah3, al0, al1, al2, al3;
                LDMATRIX_X4(ah0, ah1, ah2, ah3, abase + sw);
                LDMATRIX_X4(al0, al1, al2, al3, abase + 8192u + sw);
                const int ksg = ci * 4 + ks;
#pragma unroll
                for (int ntl = 0; ntl < 3; ntl++) {
                    const int idx = ksg * 12 + (nj * 3 + ntl) * 2;
                    ull vh = *(const ull*)(smx + ((size_t)idx * 32 + lane) * 8);
                    ull vl = *(const ull*)(smx + ((size_t)(idx + 1) * 32 + lane) * 8);
                    uint32_t bh0 = (uint32_t)vh, bh1 = (uint32_t)(vh >> 32);
                    uint32_t bl0 = (uint32_t)vl, bl1 = (uint32_t)(vl >> 32);
                    MMA_BF16(c[ntl], ah0, ah1, ah2, ah3, bh0, bh1);
                    MMA_BF16(c[ntl], al0, al1, al2, al3, bh0, bh1);
                    MMA_BF16(c[ntl], ah0, ah1, ah2, ah3, bl0, bl1);
                }
            }
        }

        // ---- redistribute C through smem (reuse A slots; stride 52 floats) ----
        __syncthreads();
        float* Cb = (float*)(smx + ABUF_OFF);
        {
            const int r0 = mi * 16 + gid;
#pragma unroll
            for (int ntl = 0; ntl < 3; ntl++) {
                const int col = nj * 24 + ntl * 8 + 2 * tig;
                *(float2*)&Cb[r0 * 52 + col]       = make_float2(c[ntl][0], c[ntl][1]);
                *(float2*)&Cb[(r0 + 8) * 52 + col] = make_float2(c[ntl][2], c[ntl][3]);
            }
        }
        __syncthreads();

        // ---- GRU epilogue: thread = (b_ep, 4 units) ----
        {
            float acc[12];
#pragma unroll
            for (int q = 0; q < 3; q++)
                *(float4*)&acc[q * 4] = *(const float4*)&Cb[b_ep * 52 + usub * 12 + q * 4];
            const float* sb = (const float*)(smx + BIAS_OFF) + usub * 12;
            const int tt = dir ? (NT - 1 - s) : s;

            float hn[4];
            __nv_bfloat16 hi4[4], lo4[4];
#pragma unroll
            for (int ul = 0; ul < 4; ul++) {
                float z = 1.f / (1.f + expf(-(gxv[ul * 3 + 0] + acc[ul * 3 + 0] + sb[ul * 3 + 0])));
                float r = 1.f / (1.f + expf(-(gxv[ul * 3 + 1] + acc[ul * 3 + 1] + sb[ul * 3 + 1])));
                float hh = tanhf(gxv[ul * 3 + 2] + r * (acc[ul * 3 + 2] + sb[ul * 3 + 2]));
                float v = z * hp[ul] + (1.f - z) * hh;
                if (!m) v = hp[ul];
                hn[ul] = v;
                __nv_bfloat16 hi = __float2bfloat16(v);
                hi4[ul] = hi;
                lo4[ul] = __float2bfloat16(v - __bfloat162float(hi));
            }
            const int uo = ubase + usub * 4;
            *(float4*)(out + ((size_t)b_ep * NT + tt) * (2 * UNITS) + dir * UNITS + uo)
                = *(const float4*)hn;
            *(float4*)(&g_h[dir][ppn][b_ep][uo]) = *(const float4*)hn;
            *(uint2*)(&g_hbf[0][dir][ppn][b_ep][uo]) = *(const uint2*)hi4;
            *(uint2*)(&g_hbf[1][dir][ppn][b_ep][uo]) = *(const uint2*)lo4;
        }

        grid_barrier((unsigned)(s + 1));
    }

    // ---- fused final state: tanh(concat(hf,hb) @ Wp + bp), h b-major, pp=0 ----
    {
        float* sst = (float*)smx;             // [64][132] staging (reuses everything)
        const int tx8 = tid & 7;
        const int tyS = tid >> 3;
        const int b0 = tyS * 2;
        const int ocol = blk * 8 + tx8;
        const float* wp = Wp + ocol;
        float acc0 = 0.f, acc1 = 0.f;
        for (int k0 = 0; k0 < 2 * UNITS; k0 += 128) {
            __syncthreads();
#pragma unroll
            for (int j = 0; j < 8; j++) {
                int f = tid + j * 256;
                int b = f >> 5;
                int k4 = (f & 31) << 2;
                int gk = k0 + k4;
                float4 v = __ldcg((const float4*)(&g_h[gk >> 10][0][b][gk & 1023]));
                *(float4*)&sst[b * 132 + k4] = v;
            }
            __syncthreads();
#pragma unroll 8
            for (int kk = 0; kk < 128; kk++) {
                float w = __ldg(wp + (size_t)(k0 + kk) * UNITS);
                acc0 = fmaf(sst[b0 * 132 + kk], w, acc0);
                acc1 = fmaf(sst[(b0 + 1) * 132 + kk], w, acc1);
            }
        }
        float bpv = bp[ocol];
        const size_t so = (size_t)NB * NT * (2 * UNITS);
        out[so + (size_t)b0 * UNITS + ocol]       = tanhf(acc0 + bpv);
        out[so + (size_t)(b0 + 1) * UNITS + ocol] = tanhf(acc1 + bpv);
    }
}

// ---------------- launch --------------------------------------------------------------
extern "C" void kernel_launch(void* const* d_in, const int* in_sizes, int n_in,
                              void* d_out, int out_size) {
    (void)in_sizes; (void)n_in; (void)out_size;
    const int*   x      = (const int*)  d_in[0];
    const float* hidden = (const float*)d_in[1];
    const float* emb    = (const float*)d_in[2];
    const float* Wf     = (const float*)d_in[3];
    const float* Uf     = (const float*)d_in[4];
    const float* bf_in  = (const float*)d_in[5];
    const float* bf_rec = (const float*)d_in[6];
    const float* Wb     = (const float*)d_in[7];
    const float* Ub     = (const float*)d_in[8];
    const float* bb_in  = (const float*)d_in[9];
    const float* bb_rec = (const float*)d_in[10];
    const float* Wp     = (const float*)d_in[11];
    const float* bp     = (const float*)d_in[12];
    float* out = (float*)d_out;

    cudaFuncSetAttribute(recurrent_kernel,
                         cudaFuncAttributeMaxDynamicSharedMemorySize, REC_SMEM_BYTES);

    prep_kernel<<<4096, 256>>>(x, hidden, Wf, Uf, Wb, Ub);
    dim3 ggx(G3 / 64, NT, 2);
    gx_kernel<<<ggx, 256>>>(x, emb, bf_in, bb_in);
    recurrent_kernel<<<REC_BLOCKS, 256, REC_SMEM_BYTES>>>(bf_rec, bb_rec, Wp, bp, out);
}

// round 10
// speedup vs baseline: 3.6292x; 1.1423x over previous
#include <cuda_runtime.h>
#include <cuda_bf16.h>
#include <cstdint>
#include <math.h>

#define VOCAB 32000
#define EMB   256
#define UNITS 1024
#define NB    64
#define NT    256
#define G3    3072
#define REC_BLOCKS 128

typedef unsigned long long ull;

// ---------------- device scratch ---------------------------------------------------
__device__ float g_gx[(size_t)2 * NT * NB * G3];         // packed gate-major inputs
__device__ __nv_bfloat16 g_ubfT[2][2][G3][UNITS];        // [split][dir][p][k] U^T hi/lo
__device__ ull  g_wbfF[2 * 16 * 384 * 2 * 32];           // frag-ordered W [dir][ks][pt][sp][lane]
__device__ __nv_bfloat16 g_embbf[2][VOCAB][EMB];         // emb hi/lo
__device__ float g_h [2][2][NB][UNITS];                  // fp32 h, [dir][pp][b][u]
__device__ __nv_bfloat16 g_hbf[2][2][2][NB][UNITS];      // [split][dir][pp][b][u]
__device__ unsigned char g_mask[2][NT][NB];
__device__ unsigned g_bar_count;
__device__ unsigned g_bar_gen;
__device__ unsigned g_cnt2[2][32];                       // per-dir barrier (padded lines)
__device__ unsigned g_gen2[2][32];

// ---------------- helpers -----------------------------------------------------------
__device__ __forceinline__ uint32_t smem_u32(const void* p) {
    uint32_t a;
    asm("{ .reg .u64 t; cvta.to.shared.u64 t, %1; cvt.u32.u64 %0, t; }" : "=r"(a) : "l"(p));
    return a;
}
__device__ __forceinline__ unsigned short bfbits(__nv_bfloat16 v) {
    return *(unsigned short*)&v;
}

#define CP_ASYNC16(dst, src) \
    asm volatile("cp.async.cg.shared.global [%0], [%1], 16;" :: "r"(dst), "l"(src) : "memory")
#define CP_COMMIT() asm volatile("cp.async.commit_group;" ::: "memory")
#define CP_WAIT0()  asm volatile("cp.async.wait_group 0;" ::: "memory")

#define LDMATRIX_X4(r0, r1, r2, r3, addr) \
    asm volatile("ldmatrix.sync.aligned.m8n8.x4.shared.b16 {%0,%1,%2,%3}, [%4];" \
                 : "=r"(r0), "=r"(r1), "=r"(r2), "=r"(r3) : "r"(addr))

#define MMA_BF16(c, a0, a1, a2, a3, b0, b1) \
    asm volatile("mma.sync.aligned.m16n8k16.row.col.f32.bf16.bf16.f32 " \
                 "{%0,%1,%2,%3}, {%4,%5,%6,%7}, {%8,%9}, {%0,%1,%2,%3};" \
                 : "+f"((c)[0]), "+f"((c)[1]), "+f"((c)[2]), "+f"((c)[3]) \
                 : "r"(a0), "r"(a1), "r"(a2), "r"(a3), "r"(b0), "r"(b1))

// ---------------- barriers ----------------------------------------------------------
__device__ __forceinline__ void barrier_generic(unsigned* cnt, unsigned* gen,
                                                unsigned nblk, unsigned target) {
    __syncthreads();
    if (threadIdx.x == 0) {
        unsigned prev;
        asm volatile("atom.acq_rel.gpu.add.u32 %0, [%1], 1;"
                     : "=r"(prev) : "l"(cnt) : "memory");
        if (prev == target * nblk - 1u) {
            asm volatile("st.release.gpu.u32 [%0], %1;"
                         :: "l"(gen), "r"(target) : "memory");
        } else {
            unsigned g;
            do {
                asm volatile("ld.acquire.gpu.u32 %0, [%1];"
                             : "=r"(g) : "l"(gen) : "memory");
            } while (g < target);
        }
    }
    __syncthreads();
}

// ---------------- prep ---------------------------------------------------------------
__global__ void prep_kernel(const int* __restrict__ x, const float* __restrict__ hidden,
                            const float* __restrict__ emb,
                            const float* __restrict__ Wf, const float* __restrict__ Uf,
                            const float* __restrict__ Wb, const float* __restrict__ Ub) {
    const long long NUBF = 2LL * 2 * G3 * UNITS;          // U^T hi/lo
    const long long NWF  = 2LL * 16 * 384 * 2 * 32;       // W frags
    const long long NEMB = 2LL * VOCAB * EMB;             // emb hi/lo
    const long long NM   = 2LL * NT * NB;
    const long long NH   = 2LL * NB * UNITS;
    const long long NHBF = 2LL * 2 * NB * UNITS;
    const long long total = NUBF + NWF + NEMB + NM + NH + NHBF;
    const long long stride = (long long)gridDim.x * blockDim.x;
    for (long long i = (long long)blockIdx.x * blockDim.x + threadIdx.x; i < total; i += stride) {
        if (i < NUBF) {
            int split = (int)(i / (2LL * G3 * UNITS));
            long long r1 = i - (long long)split * 2 * G3 * UNITS;
            int dir = (int)(r1 / ((long long)G3 * UNITS));
            long long r2 = r1 - (long long)dir * G3 * UNITS;
            int p = (int)(r2 / UNITS);
            int k = (int)(r2 % UNITS);
            const float* U = dir ? Ub : Uf;
            float val = U[(long long)k * G3 + (p % 3) * UNITS + p / 3];
            __nv_bfloat16 hi = __float2bfloat16(val);
            if (split == 0) g_ubfT[0][dir][p][k] = hi;
            else            g_ubfT[1][dir][p][k] = __float2bfloat16(val - __bfloat162float(hi));
        } else if (i < NUBF + NWF) {
            long long j = i - NUBF;
            int dir = (int)(j / (16LL * 384 * 64));
            int r = (int)(j % (16LL * 384 * 64));
            int ks = r / (384 * 64); r %= 384 * 64;
            int pt = r / 64; r %= 64;
            int sp = r >> 5;
            int lane = r & 31;
            int gid = lane >> 2, tig = lane & 3;
            int p = pt * 8 + gid;
            const float* W = dir ? Wb : Wf;
            const long long poff = (long long)(p % 3) * UNITS + p / 3;
            int k0 = ks * 16 + 2 * tig;
            float v0 = W[(long long)(k0 + 0) * G3 + poff];
            float v1 = W[(long long)(k0 + 1) * G3 + poff];
            float v2 = W[(long long)(k0 + 8) * G3 + poff];
            float v3 = W[(long long)(k0 + 9) * G3 + poff];
            unsigned short b0, b1, b2, b3;
            if (sp == 0) {
                b0 = bfbits(__float2bfloat16(v0)); b1 = bfbits(__float2bfloat16(v1));
                b2 = bfbits(__float2bfloat16(v2)); b3 = bfbits(__float2bfloat16(v3));
            } else {
                __nv_bfloat16 h0 = __float2bfloat16(v0), h1 = __float2bfloat16(v1);
                __nv_bfloat16 h2 = __float2bfloat16(v2), h3 = __float2bfloat16(v3);
                b0 = bfbits(__float2bfloat16(v0 - __bfloat162float(h0)));
                b1 = bfbits(__float2bfloat16(v1 - __bfloat162float(h1)));
                b2 = bfbits(__float2bfloat16(v2 - __bfloat162float(h2)));
                b3 = bfbits(__float2bfloat16(v3 - __bfloat162float(h3)));
            }
            g_wbfF[j] = (ull)b0 | ((ull)b1 << 16) | ((ull)b2 << 32) | ((ull)b3 << 48);
        } else if (i < NUBF + NWF + NEMB) {
            long long j = i - NUBF - NWF;
            int sp = (int)(j / ((long long)VOCAB * EMB));
            long long rem = j - (long long)sp * VOCAB * EMB;
            int e = (int)(rem / EMB), c = (int)(rem % EMB);
            float val = emb[(long long)e * EMB + c];
            __nv_bfloat16 hi = __float2bfloat16(val);
            if (sp == 0) g_embbf[0][e][c] = hi;
            else         g_embbf[1][e][c] = __float2bfloat16(val - __bfloat162float(hi));
        } else if (i < NUBF + NWF + NEMB + NM) {
            long long j = i - NUBF - NWF - NEMB;
            int dir = (int)(j / (NT * NB));
            int rem = (int)(j % (NT * NB));
            int s = rem / NB, b = rem % NB;
            int t = dir ? (NT - 1 - s) : s;
            g_mask[dir][s][b] = (x[b * NT + t] != 0) ? 1 : 0;
        } else if (i < NUBF + NWF + NEMB + NM + NH) {
            long long j = i - NUBF - NWF - NEMB - NM;
            int dir = (int)(j / (NB * UNITS));
            int rem = (int)(j % (NB * UNITS));
            int b = rem / UNITS, u = rem % UNITS;
            g_h[dir][0][b][u] = hidden[b * UNITS + u];
        } else {
            long long j = i - NUBF - NWF - NEMB - NM - NH;
            int split = (int)(j / (2LL * NB * UNITS));
            long long r1 = j - (long long)split * 2 * NB * UNITS;
            int dir = (int)(r1 / (NB * UNITS));
            int rem = (int)(r1 % (NB * UNITS));
            int b = rem / UNITS, u = rem % UNITS;
            float val = hidden[b * UNITS + u];
            __nv_bfloat16 hi = __float2bfloat16(val);
            if (split == 0) g_hbf[0][dir][0][b][u] = hi;
            else            g_hbf[1][dir][0][b][u] = __float2bfloat16(val - __bfloat162float(hi));
        }
    }
    if (blockIdx.x == 0 && threadIdx.x == 0) {
        g_bar_count = 0u; g_bar_gen = 0u;
        g_cnt2[0][0] = 0u; g_cnt2[1][0] = 0u;
        g_gen2[0][0] = 0u; g_gen2[1][0] = 0u;
    }
}

// ---------------- gx via HMMA: C[64x64] = xe[64x256] @ W[64x256]^T, 3-term split ----
// grid (48, NT, 2), block 256 = 8 warps (4 M-tiles x 2 N-halves of 32 cols).
#define GX_SMEM_BYTES (65536 + 512)
__global__ __launch_bounds__(256) void gx_kernel(const int* __restrict__ x,
                                                 const float* __restrict__ bf_in,
                                                 const float* __restrict__ bb_in) {
    extern __shared__ char smx[];
    const uint32_t smb = smem_u32(smx);
    int* toks = (int*)(smx + 65536);

    const int ct  = blockIdx.x;
    const int t   = blockIdx.y;
    const int dir = blockIdx.z;
    const int tid = threadIdx.x;
    const int wid = tid >> 5;
    const int lane = tid & 31;
    const int mi = wid & 3;
    const int nj = wid >> 2;
    const int gid = lane >> 2;
    const int tig = lane & 3;

    if (tid < 64) {
        int tt = dir ? (NT - 1 - t) : t;
        toks[tid] = x[tid * NT + tt];
    }
    __syncthreads();

    // stage A (xe hi/lo), swizzled 16B granules in 512B rows
#pragma unroll
    for (int j = 0; j < 16; j++) {
        int f = tid + j * 256;            // 0..4095
        int sp = f >> 11;
        int rem = f & 2047;
        int row = rem >> 5;
        int seg = rem & 31;
        const void* src = &g_embbf[sp][toks[row]][seg * 8];
        uint32_t dst = smb + (uint32_t)sp * 32768u + (uint32_t)(row * 512)
                     + (uint32_t)((seg ^ (row & 7)) << 4);
        CP_ASYNC16(dst, src);
    }
    CP_COMMIT();
    CP_WAIT0();
    __syncthreads();

    float c[4][4];
#pragma unroll
    for (int i = 0; i < 4; i++) { c[i][0] = 0.f; c[i][1] = 0.f; c[i][2] = 0.f; c[i][3] = 0.f; }

    const int arow = mi * 16 + (lane & 15);
    const int acb  = lane >> 4;
    const uint32_t abase = smb + (uint32_t)(arow * 512);
    const ull* wf = g_wbfF + ((size_t)dir * 16 * 384) * 64;

#pragma unroll
    for (int ks = 0; ks < 16; ks++) {
        const int seg = ks * 2 + acb;
        const uint32_t sw = (uint32_t)((seg ^ (arow & 7)) << 4);
        uint32_t ah0, ah1, ah2, ah3, al0, al1, al2, al3;
        LDMATRIX_X4(ah0, ah1, ah2, ah3, abase + sw);
        LDMATRIX_X4(al0, al1, al2, al3, abase + 32768u + sw);
        ull vh[4], vl[4];
#pragma unroll
        for (int ntl = 0; ntl < 4; ntl++) {
            size_t idx = ((size_t)ks * 384 + ct * 8 + nj * 4 + ntl) * 64 + lane;
            vh[ntl] = __ldg(wf + idx);
            vl[ntl] = __ldg(wf + idx + 32);
        }
#pragma unroll
        for (int ntl = 0; ntl < 4; ntl++)
            MMA_BF16(c[ntl], ah0, ah1, ah2, ah3, (uint32_t)vh[ntl], (uint32_t)(vh[ntl] >> 32));
#pragma unroll
        for (int ntl = 0; ntl < 4; ntl++)
            MMA_BF16(c[ntl], al0, al1, al2, al3, (uint32_t)vh[ntl], (uint32_t)(vh[ntl] >> 32));
#pragma unroll
        for (int ntl = 0; ntl < 4; ntl++)
            MMA_BF16(c[ntl], ah0, ah1, ah2, ah3, (uint32_t)vl[ntl], (uint32_t)(vl[ntl] >> 32));
    }

    // redistribute C through smem
    __syncthreads();
    float* Cb = (float*)smx;              // [64][68]
    {
        const int r0 = mi * 16 + gid;
#pragma unroll
        for (int ntl = 0; ntl < 4; ntl++) {
            const int col = nj * 32 + ntl * 8 + 2 * tig;
            *(float2*)&Cb[r0 * 68 + col]       = make_float2(c[ntl][0], c[ntl][1]);
            *(float2*)&Cb[(r0 + 8) * 68 + col] = make_float2(c[ntl][2], c[ntl][3]);
        }
    }
    __syncthreads();

    // epilogue: + b_in, write packed gx
    {
        const int b   = tid & 63;
        const int grp = tid >> 6;         // 16 cols each
        const int pbase = ct * 64;
        const float* bsrc = dir ? bb_in : bf_in;
        float o[16];
#pragma unroll
        for (int q = 0; q < 16; q++) {
            int p = pbase + grp * 16 + q;
            o[q] = Cb[b * 68 + grp * 16 + q] + __ldg(bsrc + (p % 3) * UNITS + p / 3);
        }
        float* gxp = g_gx + ((size_t)(dir * NT + t) * NB + b) * G3 + pbase + grp * 16;
#pragma unroll
        for (int q = 0; q < 4; q++)
            *(float4*)(gxp + q * 4) = *(const float4*)&o[q * 4];
    }
}

// ---------------- persistent HMMA recurrent kernel -----------------------------------
#define ABUF_OFF    196608u
#define BIAS_OFF    229376u
#define REC_SMEM_BYTES 229568

__global__ __launch_bounds__(256, 1) void recurrent_kernel(const float* __restrict__ bf_rec,
                                                           const float* __restrict__ bb_rec,
                                                           const float* __restrict__ Wp,
                                                           const float* __restrict__ bp,
                                                           float* __restrict__ out) {
    extern __shared__ char smx[];
    const uint32_t smb = smem_u32(smx);

    const int blk   = blockIdx.x;
    const int dir   = blk >> 6;
    const int utile = blk & 63;
    const int pbase = utile * 48;
    const int ubase = utile * 16;
    const int tid  = threadIdx.x;
    const int wid  = tid >> 5;
    const int lane = tid & 31;
    const int mi = wid & 3;
    const int nj = wid >> 2;
    const int gid = lane >> 2;
    const int tig = lane & 3;

    if (tid < 48) {
        const float* brec = dir ? bb_rec : bf_rec;
        ((float*)(smx + BIAS_OFF))[tid] = brec[(tid % 3) * UNITS + ubase + tid / 3];
    }

    // fragment-ordered U in smem: [ks 0..63][ntile 0..5][split][lane] x 8B
    for (int e = wid; e < 768; e += 8) {
        int ks = e / 12;
        int r  = e % 12;
        int nt = r >> 1;
        int sp = r & 1;
        int p  = pbase + nt * 8 + gid;
        const __nv_bfloat16* up = &g_ubfT[sp][dir][p][ks * 16 + 2 * tig];
        uint32_t b0 = *(const uint32_t*)up;
        uint32_t b1 = *(const uint32_t*)(up + 8);
        ull v = (ull)b0 | ((ull)b1 << 32);
        *(ull*)(smx + ((size_t)e * 32 + lane) * 8) = v;
    }
    __syncthreads();

    const int b_ep = tid & 63;
    const int usub = tid >> 6;

    for (int s = 0; s < NT; s++) {
        const int pp  = s & 1;
        const int ppn = pp ^ 1;

        float gxv[12];
        {
            const float* gxr = g_gx + ((size_t)(dir * NT + s) * NB + b_ep) * G3 + pbase + usub * 12;
#pragma unroll
            for (int q = 0; q < 3; q++)
                *(float4*)&gxv[q * 4] = __ldcs((const float4*)(gxr + q * 4));
        }
        float hp[4];
        *(float4*)hp = __ldcg((const float4*)(&g_h[dir][pp][b_ep][ubase + usub * 4]));
        const int m = g_mask[dir][s][b_ep];

        // stage chunk 0
        {
#pragma unroll
            for (int j = 0; j < 4; j++) {
                int f = tid + j * 256;
                int sp = f >> 9, row = (f >> 3) & 63, seg = f & 7;
                const void* src = &g_hbf[sp][dir][pp][row][seg * 8];
                uint32_t dst = smb + ABUF_OFF + (uint32_t)sp * 8192u
                             + (uint32_t)(row * 128) + (uint32_t)((seg ^ (row & 7)) * 16);
                CP_ASYNC16(dst, src);
            }
            CP_COMMIT();
        }

        float c[3][4];
#pragma unroll
        for (int i = 0; i < 3; i++) { c[i][0] = 0.f; c[i][1] = 0.f; c[i][2] = 0.f; c[i][3] = 0.f; }

        const int arow = mi * 16 + (lane & 15);
        const int acb  = lane >> 4;

        for (int ci = 0; ci < 16; ci++) {
            CP_WAIT0();
            __syncthreads();
            if (ci < 15) {
                const int slot = (ci + 1) & 1;
#pragma unroll
                for (int j = 0; j < 4; j++) {
                    int f = tid + j * 256;
                    int sp = f >> 9, row = (f >> 3) & 63, seg = f & 7;
                    const void* src = &g_hbf[sp][dir][pp][row][(ci + 1) * 64 + seg * 8];
                    uint32_t dst = smb + ABUF_OFF + (uint32_t)slot * 16384u + (uint32_t)sp * 8192u
                                 + (uint32_t)(row * 128) + (uint32_t)((seg ^ (row & 7)) * 16);
                    CP_ASYNC16(dst, src);
                }
                CP_COMMIT();
            }
            const uint32_t abase = smb + ABUF_OFF + (uint32_t)(ci & 1) * 16384u
                                 + (uint32_t)(arow * 128);
#pragma unroll
            for (int ks = 0; ks < 4; ks++) {
                const int seg = ks * 2 + acb;
                const uint32_t sw = (uint32_t)((seg ^ (arow & 7)) * 16);
                uint32_t ah0, ah1, ah2, ah3, al0, al1, al2, al3;
                LDMATRIX_X4(ah0, ah1, ah2, ah3, abase + sw);
                LDMATRIX_X4(al0, al1, al2, al3, abase + 8192u + sw);
                const int ksg = ci * 4 + ks;
                ull vh[3], vl[3];
#pragma unroll
                for (int ntl = 0; ntl < 3; ntl++) {
                    const int idx = ksg * 12 + (nj * 3 + ntl) * 2;
                    vh[ntl] = *(const ull*)(smx + ((size_t)idx * 32 + lane) * 8);
                    vl[ntl] = *(const ull*)(smx + ((size_t)(idx + 1) * 32 + lane) * 8);
                }
#pragma unroll
                for (int ntl = 0; ntl < 3; ntl++)
                    MMA_BF16(c[ntl], ah0, ah1, ah2, ah3, (uint32_t)vh[ntl], (uint32_t)(vh[ntl] >> 32));
#pragma unroll
                for (int ntl = 0; ntl < 3; ntl++)
                    MMA_BF16(c[ntl], al0, al1, al2, al3, (uint32_t)vh[ntl], (uint32_t)(vh[ntl] >> 32));
#pragma unroll
                for (int ntl = 0; ntl < 3; ntl++)
                    MMA_BF16(c[ntl], ah0, ah1, ah2, ah3, (uint32_t)vl[ntl], (uint32_t)(vl[ntl] >> 32));
            }
        }

        // redistribute C through smem
        __syncthreads();
        float* Cb = (float*)(smx + ABUF_OFF);
        {
            const int r0 = mi * 16 + gid;
#pragma unroll
            for (int ntl = 0; ntl < 3; ntl++) {
                const int col = nj * 24 + ntl * 8 + 2 * tig;
                *(float2*)&Cb[r0 * 52 + col]       = make_float2(c[ntl][0], c[ntl][1]);
                *(float2*)&Cb[(r0 + 8) * 52 + col] = make_float2(c[ntl][2], c[ntl][3]);
            }
        }
        __syncthreads();

        // GRU epilogue
        {
            float acc[12];
#pragma unroll
            for (int q = 0; q < 3; q++)
                *(float4*)&acc[q * 4] = *(const float4*)&Cb[b_ep * 52 + usub * 12 + q * 4];
            const float* sb = (const float*)(smx + BIAS_OFF) + usub * 12;
            const int tt = dir ? (NT - 1 - s) : s;

            float hn[4];
            __nv_bfloat16 hi4[4], lo4[4];
#pragma unroll
            for (int ul = 0; ul < 4; ul++) {
                float z = 1.f / (1.f + expf(-(gxv[ul * 3 + 0] + acc[ul * 3 + 0] + sb[ul * 3 + 0])));
                float r = 1.f / (1.f + expf(-(gxv[ul * 3 + 1] + acc[ul * 3 + 1] + sb[ul * 3 + 1])));
                float hh = tanhf(gxv[ul * 3 + 2] + r * (acc[ul * 3 + 2] + sb[ul * 3 + 2]));
                float v = z * hp[ul] + (1.f - z) * hh;
                if (!m) v = hp[ul];
                hn[ul] = v;
                __nv_bfloat16 hi = __float2bfloat16(v);
                hi4[ul] = hi;
                lo4[ul] = __float2bfloat16(v - __bfloat162float(hi));
            }
            const int uo = ubase + usub * 4;
            *(float4*)(out + ((size_t)b_ep * NT + tt) * (2 * UNITS) + dir * UNITS + uo)
                = *(const float4*)hn;
            *(float4*)(&g_h[dir][ppn][b_ep][uo]) = *(const float4*)hn;
            *(uint2*)(&g_hbf[0][dir][ppn][b_ep][uo]) = *(const uint2*)hi4;
            *(uint2*)(&g_hbf[1][dir][ppn][b_ep][uo]) = *(const uint2*)lo4;
        }

        barrier_generic(&g_cnt2[dir][0], &g_gen2[dir][0], 64u, (unsigned)(s + 1));
    }

    // full barrier before cross-dir final state
    barrier_generic(&g_bar_count, &g_bar_gen, 128u, 1u);

    // fused final state: tanh(concat(hf,hb) @ Wp + bp), h b-major, pp=0
    {
        float* sst = (float*)smx;
        const int tx8 = tid & 7;
        const int tyS = tid >> 3;
        const int b0 = tyS * 2;
        const int ocol = blk * 8 + tx8;
        const float* wp = Wp + ocol;
        float acc0 = 0.f, acc1 = 0.f;
        for (int k0 = 0; k0 < 2 * UNITS; k0 += 128) {
            __syncthreads();
#pragma unroll
            for (int j = 0; j < 8; j++) {
                int f = tid + j * 256;
                int b = f >> 5;
                int k4 = (f & 31) << 2;
                int gk = k0 + k4;
                float4 v = __ldcg((const float4*)(&g_h[gk >> 10][0][b][gk & 1023]));
                *(float4*)&sst[b * 132 + k4] = v;
            }
            __syncthreads();
#pragma unroll 8
            for (int kk = 0; kk < 128; kk++) {
                float w = __ldg(wp + (size_t)(k0 + kk) * UNITS);
                acc0 = fmaf(sst[b0 * 132 + kk], w, acc0);
                acc1 = fmaf(sst[(b0 + 1) * 132 + kk], w, acc1);
            }
        }
        float bpv = bp[ocol];
        const size_t so = (size_t)NB * NT * (2 * UNITS);
        out[so + (size_t)b0 * UNITS + ocol]       = tanhf(acc0 + bpv);
        out[so + (size_t)(b0 + 1) * UNITS + ocol] = tanhf(acc1 + bpv);
    }
}

// ---------------- launch --------------------------------------------------------------
extern "C" void kernel_launch(void* const* d_in, const int* in_sizes, int n_in,
                              void* d_out, int out_size) {
    (void)in_sizes; (void)n_in; (void)out_size;
    const int*   x      = (const int*)  d_in[0];
    const float* hidden = (const float*)d_in[1];
    const float* emb    = (const float*)d_in[2];
    const float* Wf     = (const float*)d_in[3];
    const float* Uf     = (const float*)d_in[4];
    const float* bf_in  = (const float*)d_in[5];
    const float* bf_rec = (const float*)d_in[6];
    const float* Wb     = (const float*)d_in[7];
    const float* Ub     = (const float*)d_in[8];
    const float* bb_in  = (const float*)d_in[9];
    const float* bb_rec = (const float*)d_in[10];
    const float* Wp     = (const float*)d_in[11];
    const float* bp     = (const float*)d_in[12];
    float* out = (float*)d_out;

    cudaFuncSetAttribute(recurrent_kernel,
                         cudaFuncAttributeMaxDynamicSharedMemorySize, REC_SMEM_BYTES);
    cudaFuncSetAttribute(gx_kernel,
                         cudaFuncAttributeMaxDynamicSharedMemorySize, GX_SMEM_BYTES);

    prep_kernel<<<4096, 256>>>(x, hidden, emb, Wf, Uf, Wb, Ub);
    dim3 ggx(48, NT, 2);
    gx_kernel<<<ggx, 256, GX_SMEM_BYTES>>>(x, bf_in, bb_in);
    recurrent_kernel<<<REC_BLOCKS, 256, REC_SMEM_BYTES>>>(bf_rec, bb_rec, Wp, bp, out);
}